// round 12
// baseline (speedup 1.0000x reference)
#include <cuda_runtime.h>
#include <math.h>

#define BATCH 256
#define TSTEPS 50
#define INSZ 400
#define G4 1024
#define GAMMA 0.95f
#define EPSF 1e-8f

// ---------- device scratch ----------
__device__ float g_xw[TSTEPS * BATCH * G4];
__device__ float g_h[BATCH * 256];
__device__ float g_c[BATCH * 256];
__device__ float g_r[BATCH * 256];
__device__ float g_M[BATCH * 256 * 64];
__device__ float g_wr[BATCH * 4 * 256];
__device__ float g_wu[BATCH * 256];
__device__ float g_p[BATCH * 260];      // kp pre-activations (pre-bias)

__device__ __forceinline__ float sigf(float x) { return 1.0f / (1.0f + expf(-x)); }

// ---------- init ----------
__global__ void k_init() {
    int i = blockIdx.x * blockDim.x + threadIdx.x;
    if (i < BATCH * 256 * 64) g_M[i] = 1e-6f;
    if (i < BATCH * 1024) g_wr[i] = 1.0f / 256.0f;
    if (i < BATCH * 256) {
        g_h[i] = 0.0f; g_c[i] = 0.0f; g_r[i] = 0.0f;
        g_wu[i] = 1.0f / 256.0f;
    }
}

// ---------- K1: time-parallel input GEMM (R8 version) ----------
__global__ __launch_bounds__(256) void k1_xw(
    const float* __restrict__ X, const int* __restrict__ tgt,
    const float* __restrict__ Wih, const float* __restrict__ bl)
{
    __shared__ float As[16][68];
    __shared__ float Bs[16][64];
    const int tid = threadIdx.x;
    const int tx = tid & 15, ty = tid >> 4;
    const int m0 = blockIdx.y * 64, n0 = blockIdx.x * 64;
    const int arow = tid >> 2, akq = tid & 3;
    const int bk = tid >> 4, bc = tid & 15;
    float acc[4][4] = {};
    for (int kt = 0; kt < 25; kt++) {
        float4 av = *(const float4*)(X + (size_t)(m0 + arow) * INSZ + kt * 16 + akq * 4);
        As[akq * 4 + 0][arow] = av.x; As[akq * 4 + 1][arow] = av.y;
        As[akq * 4 + 2][arow] = av.z; As[akq * 4 + 3][arow] = av.w;
        *(float4*)&Bs[bk][bc * 4] =
            *(const float4*)(Wih + (size_t)(kt * 16 + bk) * G4 + n0 + bc * 4);
        __syncthreads();
#pragma unroll
        for (int k = 0; k < 16; k++) {
            float4 a = *(float4*)&As[k][ty * 4];
            float4 b = *(float4*)&Bs[k][tx * 4];
            acc[0][0] += a.x * b.x; acc[0][1] += a.x * b.y; acc[0][2] += a.x * b.z; acc[0][3] += a.x * b.w;
            acc[1][0] += a.y * b.x; acc[1][1] += a.y * b.y; acc[1][2] += a.y * b.z; acc[1][3] += a.y * b.w;
            acc[2][0] += a.z * b.x; acc[2][1] += a.z * b.y; acc[2][2] += a.z * b.z; acc[2][3] += a.z * b.w;
            acc[3][0] += a.w * b.x; acc[3][1] += a.w * b.y; acc[3][2] += a.w * b.z; acc[3][3] += a.w * b.w;
        }
        __syncthreads();
    }
#pragma unroll
    for (int i = 0; i < 4; i++) {
        int m = m0 + ty * 4 + i;
        int bb = m / TSTEPS, t = m % TSTEPS;
        const float* offrow = (t > 0) ? (Wih + (size_t)(400 + tgt[m - 1]) * G4) : (const float*)0;
        float* dst = g_xw + ((size_t)t * BATCH + bb) * G4 + n0 + tx * 4;
#pragma unroll
        for (int j = 0; j < 4; j++) {
            int c = n0 + tx * 4 + j;
            float v = acc[i][j] + bl[c];
            if (offrow) v += offrow[c];
            dst[j] = v;
        }
    }
}

// ---------- K2: recurrent GEMM + LSTM, double-buffered (R8 version, untouched) ----------
__global__ __launch_bounds__(256) void k2_step(
    const float* __restrict__ Wih, const float* __restrict__ Whh, int t)
{
    __shared__ float As[2][16][34];
    __shared__ float Bs[2][16][68];
    const int tid = threadIdx.x;
    const int tx = tid & 15, ty = tid >> 4;
    const int b0 = blockIdx.x * 32, u0 = blockIdx.y * 16;
    const int arow = tid >> 3, akq = tid & 7;
    const int bk = tid >> 4, bu = tid & 15;
    const float* WihR = Wih + (size_t)405 * G4;

    const int uP = u0 + tx;
    const int bP0 = b0 + ty * 2, bP1 = bP0 + 1;
    const float* xwA = g_xw + ((size_t)t * BATCH + bP0) * G4;
    const float* xwB = g_xw + ((size_t)t * BATCH + bP1) * G4;
    float xA0 = xwA[uP], xA1 = xwA[256 + uP], xA2 = xwA[512 + uP], xA3 = xwA[768 + uP];
    float xB0 = xwB[uP], xB1 = xwB[256 + uP], xB2 = xwB[512 + uP], xB3 = xwB[768 + uP];
    float cA = g_c[bP0 * 256 + uP], cB = g_c[bP1 * 256 + uP];

    {
        float2 av = *(const float2*)(g_r + (size_t)(b0 + arow) * 256 + akq * 2);
        As[0][akq * 2][arow] = av.x; As[0][akq * 2 + 1][arow] = av.y;
        const float* wrow = WihR + (size_t)bk * G4 + u0 + bu;
        Bs[0][bk][bu * 4 + 0] = wrow[0];
        Bs[0][bk][bu * 4 + 1] = wrow[256];
        Bs[0][bk][bu * 4 + 2] = wrow[512];
        Bs[0][bk][bu * 4 + 3] = wrow[768];
    }
    __syncthreads();

    float acc[2][4] = {};
    for (int kt = 0; kt < 32; kt++) {
        const int cur = kt & 1;
        float2 avn = make_float2(0.f, 0.f);
        float bgn0 = 0.f, bgn1 = 0.f, bgn2 = 0.f, bgn3 = 0.f;
        if (kt < 31) {
            const int kn = kt + 1;
            const float* src = (kn < 16) ? g_r : g_h;
            avn = *(const float2*)(src + (size_t)(b0 + arow) * 256 + (kn & 15) * 16 + akq * 2);
            const float* W = (kn < 16) ? WihR : Whh;
            const float* wrow = W + (size_t)((kn & 15) * 16 + bk) * G4 + u0 + bu;
            bgn0 = wrow[0]; bgn1 = wrow[256]; bgn2 = wrow[512]; bgn3 = wrow[768];
        }
#pragma unroll
        for (int k = 0; k < 16; k++) {
            float a0 = As[cur][k][ty * 2], a1 = As[cur][k][ty * 2 + 1];
            float4 b = *(float4*)&Bs[cur][k][tx * 4];
            acc[0][0] += a0 * b.x; acc[0][1] += a0 * b.y; acc[0][2] += a0 * b.z; acc[0][3] += a0 * b.w;
            acc[1][0] += a1 * b.x; acc[1][1] += a1 * b.y; acc[1][2] += a1 * b.z; acc[1][3] += a1 * b.w;
        }
        if (kt < 31) {
            const int nxt = 1 - cur;
            As[nxt][akq * 2][arow] = avn.x; As[nxt][akq * 2 + 1][arow] = avn.y;
            Bs[nxt][bk][bu * 4 + 0] = bgn0;
            Bs[nxt][bk][bu * 4 + 1] = bgn1;
            Bs[nxt][bk][bu * 4 + 2] = bgn2;
            Bs[nxt][bk][bu * 4 + 3] = bgn3;
            __syncthreads();
        }
    }
    {
        float gi = acc[0][0] + xA0, gf = acc[0][1] + xA1, gg = acc[0][2] + xA2, go = acc[0][3] + xA3;
        float cc = sigf(gf) * cA + sigf(gi) * tanhf(gg);
        g_c[bP0 * 256 + uP] = cc;
        g_h[bP0 * 256 + uP] = sigf(go) * tanhf(cc);
    }
    {
        float gi = acc[1][0] + xB0, gf = acc[1][1] + xB1, gg = acc[1][2] + xB2, go = acc[1][3] + xB3;
        float cc = sigf(gf) * cB + sigf(gi) * tanhf(gg);
        g_c[bP1 * 256 + uP] = cc;
        g_h[bP1 * 256 + uP] = sigf(go) * tanhf(cc);
    }
}

// ---------- K3P: p = h @ Wkp, column-tiled, weight-staged ----------
// grid (8, 13): 32 batches x 20 cols per CTA. smem: h[32][260] + wk[256][20]
#define K3P_FLOATS (32 * 260 + 256 * 20)
#define K3P_BYTES (K3P_FLOATS * 4)

__global__ __launch_bounds__(256) void k3p_kp(const float* __restrict__ Wkp)
{
    extern __shared__ float d3[];
    float* shh = d3;             // [32][260] (row stride 260, 16B-aligned rows)
    float* swk = d3 + 32 * 260;  // [256][20]
    const int tid = threadIdx.x;
    const int b0 = blockIdx.x * 32;
    const int cbase = blockIdx.y * 20;

    // stage h (float4, coalesced)
    for (int e = tid; e < 32 * 64; e += 256) {
        int b = e >> 6, q = e & 63;
        float4 v = *(const float4*)(g_h + (size_t)(b0 + b) * 256 + q * 4);
        float* dst = shh + b * 260 + q * 4;
        dst[0] = v.x; dst[1] = v.y; dst[2] = v.z; dst[3] = v.w;
    }
    // stage Wkp column slice
    for (int e = tid; e < 256 * 20; e += 256) {
        int k = e / 20, c = e - k * 20;
        swk[k * 20 + c] = Wkp[(size_t)k * 260 + cbase + c];
    }
    __syncthreads();

    const int b = tid >> 3, cg = tid & 7;
    const int c0 = cg, c1 = cg + 8, c2 = cg + 16;   // c2 valid iff cg < 4
    const float* hrow = shh + b * 260;
    float acc0 = 0.0f, acc1 = 0.0f, acc2 = 0.0f;
#pragma unroll 4
    for (int k = 0; k < 256; k++) {
        float hv = hrow[k];
        const float* wr = swk + k * 20;
        acc0 += hv * wr[c0];
        acc1 += hv * wr[c1];
        if (cg < 4) acc2 += hv * wr[c2];
    }
    float* gp = g_p + (size_t)(b0 + b) * 260 + cbase;
    gp[c0] = acc0;
    gp[c1] = acc1;
    if (cg < 4) gp[c2] = acc2;
}

// ---------- K4: 512-thread memory module (reads g_p; no GEMV) ----------
#define O_M     0        // 256*65
#define O_K     16640    // 256
#define O_SIM   16896    // 1024
#define O_WW    17920    // 1024
#define O_WU    18944    // 256
#define O_H     19200    // 256
#define O_RD    19456    // 256
#define O_PR    19712    // 512
#define O_WP    20224    // 40
#define O_EX    20264    // 16
#define O_SOFT  20280    // 16
#define O_LU    20296    // 4 (int)
#define K4_FLOATS 20304
#define K4_BYTES (K4_FLOATS * 4)

__global__ __launch_bounds__(512) void k4_mem(
    const float* __restrict__ bkp,
    const float* __restrict__ Wout, const float* __restrict__ bout,
    float* __restrict__ out, int t)
{
    extern __shared__ float sm[];
    float* sM     = sm + O_M;
    float* sk     = sm + O_K;
    float* ssim   = sm + O_SIM;
    float* sww    = sm + O_WW;
    float* swu    = sm + O_WU;
    float* sh     = sm + O_H;
    float* sreads = sm + O_RD;
    float* spR    = sm + O_PR;
    float* swp    = sm + O_WP;
    float* sex    = sm + O_EX;
    float* ssoft  = sm + O_SOFT;
    int*   slu    = (int*)(sm + O_LU);

    const int b = blockIdx.x;
    const int tid = threadIdx.x;
    const int lane = tid & 31, wid = tid >> 5;

    // ---- phase 0: loads + kp activation ----
    if (tid < 256) {
        swu[tid] = g_wu[b * 256 + tid];
        sh[tid]  = g_h[b * 256 + tid];
    }
    if (tid < 260) {
        float s = g_p[(size_t)b * 260 + tid] + bkp[tid];
        if (tid < 256) sk[tid] = tanhf(s);
        else sex[4 + (tid - 256)] = sigf(s);
    }
    {
        const float4* gm4 = (const float4*)(g_M + (size_t)b * 16384);
#pragma unroll
        for (int e = 0; e < 8; e++) {
            float4 v = gm4[e * 512 + tid];
            int gidx = (e * 512 + tid) * 4;
            int n = gidx >> 6, d = gidx & 63;
            float* dst = sM + n * 65 + d;
            dst[0] = v.x; dst[1] = v.y; dst[2] = v.z; dst[3] = v.w;
        }
    }
    __syncthreads();

    // key norms (warps 0-3) || top-4 least-used (warp 4)
    if (wid < 4) {
        float v0 = sk[wid * 64 + lane], v1 = sk[wid * 64 + lane + 32];
        float s = v0 * v0 + v1 * v1;
#pragma unroll
        for (int o = 16; o > 0; o >>= 1) s += __shfl_xor_sync(0xffffffffu, s, o);
        if (lane == 0) sex[wid] = 1.0f / (sqrtf(s) + EPSF);
    } else if (wid == 4) {
        float v[8];
#pragma unroll
        for (int j = 0; j < 8; j++) v[j] = swu[j * 32 + lane];
#pragma unroll
        for (int r = 0; r < 4; r++) {
            float bv = v[0]; int bi = lane;
#pragma unroll
            for (int j = 1; j < 8; j++) {
                int idx = j * 32 + lane;
                if (v[j] < bv) { bv = v[j]; bi = idx; }
            }
#pragma unroll
            for (int o = 16; o > 0; o >>= 1) {
                float ov = __shfl_xor_sync(0xffffffffu, bv, o);
                int   oi = __shfl_xor_sync(0xffffffffu, bi, o);
                if (ov < bv || (ov == bv && oi < bi)) { bv = ov; bi = oi; }
            }
            if (lane == 0) slu[r] = bi;
#pragma unroll
            for (int j = 0; j < 8; j++)
                if (bi == j * 32 + lane) v[j] = 3.0e38f;
        }
    }
    __syncthreads();

    if (tid < 256) {
        float a0 = sex[4], a1 = sex[5], a2 = sex[6], a3 = sex[7];
        const float* wr = g_wr + (size_t)b * 1024;
        float4 w;
        w.x = a0 * wr[tid]       + (1.0f - a0) * ((tid == slu[0]) ? 1.0f : 0.0f);
        w.y = a1 * wr[256 + tid] + (1.0f - a1) * ((tid == slu[1]) ? 1.0f : 0.0f);
        w.z = a2 * wr[512 + tid] + (1.0f - a2) * ((tid == slu[2]) ? 1.0f : 0.0f);
        w.w = a3 * wr[768 + tid] + (1.0f - a3) * ((tid == slu[3]) ? 1.0f : 0.0f);
        *(float4*)&sww[tid * 4] = w;
    }
    __syncthreads();

    // erase + additive write; persist M
    {
        const int d = tid & 63, nb = tid >> 6;
        const int lu0 = slu[0];
        const float k0 = sk[d], k1 = sk[64 + d], k2 = sk[128 + d], k3 = sk[192 + d];
        float* gmw = g_M + (size_t)b * 16384;
#pragma unroll 4
        for (int e = 0; e < 32; e++) {
            int n = e * 8 + nb;
            float4 w = *(float4*)&sww[n * 4];
            float v = (n == lu0) ? 0.0f : sM[n * 65 + d];
            v += w.x * k0 + w.y * k1 + w.z * k2 + w.w * k3;
            sM[n * 65 + d] = v;
            gmw[n * 64 + d] = v;
        }
    }
    __syncthreads();

    // row norms + cosine sims: 2 threads per row
    {
        const int row = tid >> 1, hf = tid & 1;
        const float* mrow = sM + row * 65 + hf * 32;
        const float* kb = sk + hf * 32;
        float s = 0, d0 = 0, d1 = 0, d2 = 0, d3 = 0;
#pragma unroll
        for (int dd = 0; dd < 32; dd += 4) {
            float4 kk0 = *(const float4*)&kb[dd];
            float4 kk1 = *(const float4*)&kb[64 + dd];
            float4 kk2 = *(const float4*)&kb[128 + dd];
            float4 kk3 = *(const float4*)&kb[192 + dd];
            float m0 = mrow[dd], m1 = mrow[dd + 1], m2 = mrow[dd + 2], m3 = mrow[dd + 3];
            s  += m0 * m0 + m1 * m1 + m2 * m2 + m3 * m3;
            d0 += m0 * kk0.x + m1 * kk0.y + m2 * kk0.z + m3 * kk0.w;
            d1 += m0 * kk1.x + m1 * kk1.y + m2 * kk1.z + m3 * kk1.w;
            d2 += m0 * kk2.x + m1 * kk2.y + m2 * kk2.z + m3 * kk2.w;
            d3 += m0 * kk3.x + m1 * kk3.y + m2 * kk3.z + m3 * kk3.w;
        }
        s  += __shfl_xor_sync(0xffffffffu, s, 1);
        d0 += __shfl_xor_sync(0xffffffffu, d0, 1);
        d1 += __shfl_xor_sync(0xffffffffu, d1, 1);
        d2 += __shfl_xor_sync(0xffffffffu, d2, 1);
        d3 += __shfl_xor_sync(0xffffffffu, d3, 1);
        if (hf == 0) {
            float inv = 1.0f / (sqrtf(s) + EPSF);
            ssim[row]       = d0 * inv * sex[0];
            ssim[256 + row] = d1 * inv * sex[1];
            ssim[512 + row] = d2 * inv * sex[2];
            ssim[768 + row] = d3 * inv * sex[3];
        }
    }
    __syncthreads();

    // softmax per head (warp-shuffle)
    float e0, e1, e2, e3;
    float* srow = 0;
    int gH = 0;
    if (tid < 256) {
        gH = tid >> 6;
        const int j = tid & 63;
        srow = ssim + gH * 256 + j;
        float v0 = srow[0], v1 = srow[64], v2 = srow[128], v3 = srow[192];
        float mx = fmaxf(fmaxf(v0, v1), fmaxf(v2, v3));
#pragma unroll
        for (int o = 16; o > 0; o >>= 1) mx = fmaxf(mx, __shfl_xor_sync(0xffffffffu, mx, o));
        if (lane == 0) ssoft[gH * 2 + ((tid >> 5) & 1)] = mx;
        e0 = v0; e1 = v1; e2 = v2; e3 = v3;
    }
    __syncthreads();
    if (tid < 256) {
        float mx = fmaxf(ssoft[gH * 2], ssoft[gH * 2 + 1]);
        e0 = expf(e0 - mx); e1 = expf(e1 - mx); e2 = expf(e2 - mx); e3 = expf(e3 - mx);
        float sum = e0 + e1 + e2 + e3;
#pragma unroll
        for (int o = 16; o > 0; o >>= 1) sum += __shfl_xor_sync(0xffffffffu, sum, o);
        if (lane == 0) ssoft[8 + gH * 2 + ((tid >> 5) & 1)] = sum;
    }
    __syncthreads();
    if (tid < 256) {
        float inv = 1.0f / (ssoft[8 + gH * 2] + ssoft[8 + gH * 2 + 1]);
        srow[0] = e0 * inv; srow[64] = e1 * inv; srow[128] = e2 * inv; srow[192] = e3 * inv;
        float wrs = (e0 + e1 + e2 + e3) * inv;
        float4 w = *(float4*)&sww[tid * 4];
        g_wu[b * 256 + tid] = GAMMA * swu[tid] + wrs + (w.x + w.y + w.z + w.w);
    }
    __syncthreads();
    if (tid < 256) {
        float* gwr = g_wr + (size_t)b * 1024;
        gwr[tid] = ssim[tid]; gwr[256 + tid] = ssim[256 + tid];
        gwr[512 + tid] = ssim[512 + tid]; gwr[768 + tid] = ssim[768 + tid];
    }

    // reads[r][d]
    {
        const int half = tid >> 8;
        const int r = (tid >> 6) & 3, dd = tid & 63;
        const float* wr2 = ssim + r * 256 + half * 128;
        const float* mbase = sM + half * 128 * 65;
        float acc = 0.0f;
#pragma unroll 4
        for (int n = 0; n < 128; n += 4) {
            float4 w = *(const float4*)&wr2[n];
            acc += w.x * mbase[n * 65 + dd] + w.y * mbase[(n + 1) * 65 + dd]
                 + w.z * mbase[(n + 2) * 65 + dd] + w.w * mbase[(n + 3) * 65 + dd];
        }
        spR[tid] = acc;
    }
    __syncthreads();
    if (tid < 256) {
        float v = spR[tid] + spR[tid + 256];
        sreads[tid] = v;
        g_r[b * 256 + tid] = v;
    }
    __syncthreads();

    // output head
    if (tid < 256) {
        const float* w1 = Wout + (size_t)tid * 5;
        const float* w2 = Wout + (size_t)(256 + tid) * 5;
        float hv = sh[tid], rv = sreads[tid];
        float p0 = hv * w1[0] + rv * w2[0];
        float p1 = hv * w1[1] + rv * w2[1];
        float p2 = hv * w1[2] + rv * w2[2];
        float p3 = hv * w1[3] + rv * w2[3];
        float p4 = hv * w1[4] + rv * w2[4];
#pragma unroll
        for (int o = 16; o > 0; o >>= 1) {
            p0 += __shfl_xor_sync(0xffffffffu, p0, o);
            p1 += __shfl_xor_sync(0xffffffffu, p1, o);
            p2 += __shfl_xor_sync(0xffffffffu, p2, o);
            p3 += __shfl_xor_sync(0xffffffffu, p3, o);
            p4 += __shfl_xor_sync(0xffffffffu, p4, o);
        }
        if (lane == 0) {
            swp[wid * 5 + 0] = p0; swp[wid * 5 + 1] = p1; swp[wid * 5 + 2] = p2;
            swp[wid * 5 + 3] = p3; swp[wid * 5 + 4] = p4;
        }
    }
    __syncthreads();
    if (tid == 0) {
        float l[5];
#pragma unroll
        for (int c = 0; c < 5; c++) {
            float s = bout[c];
#pragma unroll
            for (int w = 0; w < 8; w++) s += swp[w * 5 + c];
            l[c] = s;
        }
        float mx = l[0];
#pragma unroll
        for (int c = 1; c < 5; c++) mx = fmaxf(mx, l[c]);
        float e[5], s = 0.0f;
#pragma unroll
        for (int c = 0; c < 5; c++) { e[c] = expf(l[c] - mx); s += e[c]; }
        float inv = 1.0f / s;
        float* o = out + ((size_t)b * TSTEPS + t) * 5;
#pragma unroll
        for (int c = 0; c < 5; c++) o[c] = e[c] * inv;
    }
}

// ---------- launch ----------
extern "C" void kernel_launch(void* const* d_in, const int* in_sizes, int n_in,
                              void* d_out, int out_size) {
    const float* X    = (const float*)d_in[0];
    const int*   tgt  = (const int*)d_in[1];
    const float* Wih  = (const float*)d_in[2];
    const float* Whh  = (const float*)d_in[3];
    const float* bl   = (const float*)d_in[4];
    const float* Wkp  = (const float*)d_in[5];
    const float* bkp  = (const float*)d_in[6];
    const float* Wout = (const float*)d_in[7];
    const float* bout = (const float*)d_in[8];
    float* out = (float*)d_out;

    cudaFuncSetAttribute(k3p_kp, cudaFuncAttributeMaxDynamicSharedMemorySize, K3P_BYTES);
    cudaFuncSetAttribute(k4_mem, cudaFuncAttributeMaxDynamicSharedMemorySize, K4_BYTES);

    k_init<<<16384, 256>>>();
    k1_xw<<<dim3(16, 200), 256>>>(X, tgt, Wih, bl);
    for (int t = 0; t < TSTEPS; t++) {
        k2_step<<<dim3(8, 16), 256>>>(Wih, Whh, t);
        k3p_kp<<<dim3(8, 13), 256, K3P_BYTES>>>(Wkp);
        k4_mem<<<256, 512, K4_BYTES>>>(bkp, Wout, bout, out, t);
    }
}

// round 13
// speedup vs baseline: 1.1734x; 1.1734x over previous
#include <cuda_runtime.h>
#include <math.h>

#define BATCH 256
#define TSTEPS 50
#define INSZ 400
#define G4 1024
#define GAMMA 0.95f
#define EPSF 1e-8f

// ---------- device scratch ----------
__device__ float g_xw[TSTEPS * BATCH * G4];
__device__ float g_h[BATCH * 256];
__device__ float g_c[BATCH * 256];
__device__ float g_r[BATCH * 256];
__device__ float g_M[BATCH * 256 * 64];
__device__ float g_wr[BATCH * 4 * 256];
__device__ float g_wu[BATCH * 256];

__device__ __forceinline__ float sigf(float x) { return 1.0f / (1.0f + expf(-x)); }

__device__ __forceinline__ unsigned tf32cvt(float f) {
    unsigned u;
    asm("cvt.rna.tf32.f32 %0, %1;" : "=r"(u) : "f"(f));
    return u;
}
__device__ __forceinline__ void mma_tf32(
    float& d0, float& d1, float& d2, float& d3,
    unsigned a0, unsigned a1, unsigned a2, unsigned a3,
    unsigned b0, unsigned b1)
{
    asm("mma.sync.aligned.m16n8k8.row.col.f32.tf32.tf32.f32 "
        "{%0,%1,%2,%3}, {%4,%5,%6,%7}, {%8,%9}, {%0,%1,%2,%3};"
        : "+f"(d0), "+f"(d1), "+f"(d2), "+f"(d3)
        : "r"(a0), "r"(a1), "r"(a2), "r"(a3), "r"(b0), "r"(b1));
}

// ---------- init ----------
__global__ void k_init() {
    int i = blockIdx.x * blockDim.x + threadIdx.x;
    if (i < BATCH * 256 * 64) g_M[i] = 1e-6f;
    if (i < BATCH * 1024) g_wr[i] = 1.0f / 256.0f;
    if (i < BATCH * 256) {
        g_h[i] = 0.0f; g_c[i] = 0.0f; g_r[i] = 0.0f;
        g_wu[i] = 1.0f / 256.0f;
    }
}

// ---------- K1: tf32 tensor-core GEMM [12800,400]@[400,1024] ----------
// CTA tile 128x128, 8 warps (4M x 2N), warp tile 32x64, K staged 16 (double buffer).
__global__ __launch_bounds__(256) void k1_xw_tc(
    const float* __restrict__ X, const int* __restrict__ tgt,
    const float* __restrict__ Wih, const float* __restrict__ bl)
{
    __shared__ unsigned As[2][128][20];     // [m][k], stride 20: conflict-free frag loads
    __shared__ unsigned Bs[2][16][136];     // [k][n], stride 136: conflict-free frag loads
    __shared__ float bls[128];

    const int tid = threadIdx.x;
    const int lane = tid & 31, warp = tid >> 5;
    const int wm = warp & 3, wn = warp >> 2;      // 4 M-warps x 2 N-warps
    const int g = lane >> 2, tg = lane & 3;
    const int m0 = blockIdx.y * 128, n0 = blockIdx.x * 128;

    if (tid < 128) bls[tid] = bl[n0 + tid];

    // loader mapping (2 float4 each for A and B per chunk)
    const int e0 = tid, e1 = tid + 256;
    const int arw0 = e0 >> 2, acq0 = e0 & 3;
    const int arw1 = e1 >> 2, acq1 = e1 & 3;
    const int bk0 = e0 >> 5, bnq0 = e0 & 31;
    const int bk1 = e1 >> 5, bnq1 = e1 & 31;

    float4 ax0, ax1, bx0, bx1;

    // preload chunk 0 -> buffer 0
    ax0 = *(const float4*)(X + (size_t)(m0 + arw0) * INSZ + acq0 * 4);
    ax1 = *(const float4*)(X + (size_t)(m0 + arw1) * INSZ + acq1 * 4);
    bx0 = *(const float4*)(Wih + (size_t)bk0 * G4 + n0 + bnq0 * 4);
    bx1 = *(const float4*)(Wih + (size_t)bk1 * G4 + n0 + bnq1 * 4);
    {
        uint4 u;
        u.x = tf32cvt(ax0.x); u.y = tf32cvt(ax0.y); u.z = tf32cvt(ax0.z); u.w = tf32cvt(ax0.w);
        *(uint4*)&As[0][arw0][acq0 * 4] = u;
        u.x = tf32cvt(ax1.x); u.y = tf32cvt(ax1.y); u.z = tf32cvt(ax1.z); u.w = tf32cvt(ax1.w);
        *(uint4*)&As[0][arw1][acq1 * 4] = u;
        u.x = tf32cvt(bx0.x); u.y = tf32cvt(bx0.y); u.z = tf32cvt(bx0.z); u.w = tf32cvt(bx0.w);
        *(uint4*)&Bs[0][bk0][bnq0 * 4] = u;
        u.x = tf32cvt(bx1.x); u.y = tf32cvt(bx1.y); u.z = tf32cvt(bx1.z); u.w = tf32cvt(bx1.w);
        *(uint4*)&Bs[0][bk1][bnq1 * 4] = u;
    }
    __syncthreads();

    float d[2][8][4];
#pragma unroll
    for (int i = 0; i < 2; i++)
#pragma unroll
        for (int j = 0; j < 8; j++)
#pragma unroll
            for (int q = 0; q < 4; q++) d[i][j][q] = 0.0f;

    for (int kt = 0; kt < 25; kt++) {
        const int cur = kt & 1;
        if (kt < 24) {
            const int kb = (kt + 1) * 16;
            ax0 = *(const float4*)(X + (size_t)(m0 + arw0) * INSZ + kb + acq0 * 4);
            ax1 = *(const float4*)(X + (size_t)(m0 + arw1) * INSZ + kb + acq1 * 4);
            bx0 = *(const float4*)(Wih + (size_t)(kb + bk0) * G4 + n0 + bnq0 * 4);
            bx1 = *(const float4*)(Wih + (size_t)(kb + bk1) * G4 + n0 + bnq1 * 4);
        }
#pragma unroll
        for (int ks = 0; ks < 2; ks++) {
            const int kk = ks * 8;
            unsigned af[2][4];
#pragma unroll
            for (int mt = 0; mt < 2; mt++) {
                const int r = wm * 32 + mt * 16 + g;
                af[mt][0] = As[cur][r][kk + tg];
                af[mt][1] = As[cur][r + 8][kk + tg];
                af[mt][2] = As[cur][r][kk + tg + 4];
                af[mt][3] = As[cur][r + 8][kk + tg + 4];
            }
#pragma unroll
            for (int nt = 0; nt < 8; nt++) {
                const int c = wn * 64 + nt * 8 + g;
                unsigned b0 = Bs[cur][kk + tg][c];
                unsigned b1 = Bs[cur][kk + tg + 4][c];
                mma_tf32(d[0][nt][0], d[0][nt][1], d[0][nt][2], d[0][nt][3],
                         af[0][0], af[0][1], af[0][2], af[0][3], b0, b1);
                mma_tf32(d[1][nt][0], d[1][nt][1], d[1][nt][2], d[1][nt][3],
                         af[1][0], af[1][1], af[1][2], af[1][3], b0, b1);
            }
        }
        if (kt < 24) {
            const int nxt = 1 - cur;
            uint4 u;
            u.x = tf32cvt(ax0.x); u.y = tf32cvt(ax0.y); u.z = tf32cvt(ax0.z); u.w = tf32cvt(ax0.w);
            *(uint4*)&As[nxt][arw0][acq0 * 4] = u;
            u.x = tf32cvt(ax1.x); u.y = tf32cvt(ax1.y); u.z = tf32cvt(ax1.z); u.w = tf32cvt(ax1.w);
            *(uint4*)&As[nxt][arw1][acq1 * 4] = u;
            u.x = tf32cvt(bx0.x); u.y = tf32cvt(bx0.y); u.z = tf32cvt(bx0.z); u.w = tf32cvt(bx0.w);
            *(uint4*)&Bs[nxt][bk0][bnq0 * 4] = u;
            u.x = tf32cvt(bx1.x); u.y = tf32cvt(bx1.y); u.z = tf32cvt(bx1.z); u.w = tf32cvt(bx1.w);
            *(uint4*)&Bs[nxt][bk1][bnq1 * 4] = u;
            __syncthreads();
        }
    }

    // epilogue: bias + one-hot offset row-select, scatter to g_xw[t][b][:]
#pragma unroll
    for (int mt = 0; mt < 2; mt++) {
#pragma unroll
        for (int rp = 0; rp < 2; rp++) {
            const int m = m0 + wm * 32 + mt * 16 + g + rp * 8;
            const int bb = m / TSTEPS, t = m % TSTEPS;
            const float* offrow = (t > 0) ? (Wih + (size_t)(400 + tgt[m - 1]) * G4) : (const float*)0;
            float* dst = g_xw + ((size_t)t * BATCH + bb) * G4 + n0;
#pragma unroll
            for (int nt = 0; nt < 8; nt++) {
                const int c = wn * 64 + nt * 8 + tg * 2;
                float v0 = d[mt][nt][rp * 2 + 0] + bls[c];
                float v1 = d[mt][nt][rp * 2 + 1] + bls[c + 1];
                if (offrow) { v0 += offrow[n0 + c]; v1 += offrow[n0 + c + 1]; }
                float2 v = make_float2(v0, v1);
                *(float2*)(dst + c) = v;
            }
        }
    }
}

// ---------- K2: recurrent GEMM + LSTM, double-buffered (R8 version) ----------
__global__ __launch_bounds__(256) void k2_step(
    const float* __restrict__ Wih, const float* __restrict__ Whh, int t)
{
    __shared__ float As2[2][16][34];
    __shared__ float Bs2[2][16][68];
    const int tid = threadIdx.x;
    const int tx = tid & 15, ty = tid >> 4;
    const int b0 = blockIdx.x * 32, u0 = blockIdx.y * 16;
    const int arow = tid >> 3, akq = tid & 7;
    const int bk = tid >> 4, bu = tid & 15;
    const float* WihR = Wih + (size_t)405 * G4;

    const int uP = u0 + tx;
    const int bP0 = b0 + ty * 2, bP1 = bP0 + 1;
    const float* xwA = g_xw + ((size_t)t * BATCH + bP0) * G4;
    const float* xwB = g_xw + ((size_t)t * BATCH + bP1) * G4;
    float xA0 = xwA[uP], xA1 = xwA[256 + uP], xA2 = xwA[512 + uP], xA3 = xwA[768 + uP];
    float xB0 = xwB[uP], xB1 = xwB[256 + uP], xB2 = xwB[512 + uP], xB3 = xwB[768 + uP];
    float cA = g_c[bP0 * 256 + uP], cB = g_c[bP1 * 256 + uP];

    {
        float2 av = *(const float2*)(g_r + (size_t)(b0 + arow) * 256 + akq * 2);
        As2[0][akq * 2][arow] = av.x; As2[0][akq * 2 + 1][arow] = av.y;
        const float* wrow = WihR + (size_t)bk * G4 + u0 + bu;
        Bs2[0][bk][bu * 4 + 0] = wrow[0];
        Bs2[0][bk][bu * 4 + 1] = wrow[256];
        Bs2[0][bk][bu * 4 + 2] = wrow[512];
        Bs2[0][bk][bu * 4 + 3] = wrow[768];
    }
    __syncthreads();

    float acc[2][4] = {};
    for (int kt = 0; kt < 32; kt++) {
        const int cur = kt & 1;
        float2 avn = make_float2(0.f, 0.f);
        float bgn0 = 0.f, bgn1 = 0.f, bgn2 = 0.f, bgn3 = 0.f;
        if (kt < 31) {
            const int kn = kt + 1;
            const float* src = (kn < 16) ? g_r : g_h;
            avn = *(const float2*)(src + (size_t)(b0 + arow) * 256 + (kn & 15) * 16 + akq * 2);
            const float* W = (kn < 16) ? WihR : Whh;
            const float* wrow = W + (size_t)((kn & 15) * 16 + bk) * G4 + u0 + bu;
            bgn0 = wrow[0]; bgn1 = wrow[256]; bgn2 = wrow[512]; bgn3 = wrow[768];
        }
#pragma unroll
        for (int k = 0; k < 16; k++) {
            float a0 = As2[cur][k][ty * 2], a1 = As2[cur][k][ty * 2 + 1];
            float4 b = *(float4*)&Bs2[cur][k][tx * 4];
            acc[0][0] += a0 * b.x; acc[0][1] += a0 * b.y; acc[0][2] += a0 * b.z; acc[0][3] += a0 * b.w;
            acc[1][0] += a1 * b.x; acc[1][1] += a1 * b.y; acc[1][2] += a1 * b.z; acc[1][3] += a1 * b.w;
        }
        if (kt < 31) {
            const int nxt = 1 - cur;
            As2[nxt][akq * 2][arow] = avn.x; As2[nxt][akq * 2 + 1][arow] = avn.y;
            Bs2[nxt][bk][bu * 4 + 0] = bgn0;
            Bs2[nxt][bk][bu * 4 + 1] = bgn1;
            Bs2[nxt][bk][bu * 4 + 2] = bgn2;
            Bs2[nxt][bk][bu * 4 + 3] = bgn3;
            __syncthreads();
        }
    }
    {
        float gi = acc[0][0] + xA0, gf = acc[0][1] + xA1, gg = acc[0][2] + xA2, go = acc[0][3] + xA3;
        float cc = sigf(gf) * cA + sigf(gi) * tanhf(gg);
        g_c[bP0 * 256 + uP] = cc;
        g_h[bP0 * 256 + uP] = sigf(go) * tanhf(cc);
    }
    {
        float gi = acc[1][0] + xB0, gf = acc[1][1] + xB1, gg = acc[1][2] + xB2, go = acc[1][3] + xB3;
        float cc = sigf(gf) * cB + sigf(gi) * tanhf(gg);
        g_c[bP1 * 256 + uP] = cc;
        g_h[bP1 * 256 + uP] = sigf(go) * tanhf(cc);
    }
}

// ---------- K4: 512-thread memory module with inline fp32 kp GEMV (R8 version) ----------
#define O_M     0        // 256*65
#define O_K     16640    // 256
#define O_SIM   16896    // 1024
#define O_WW    17920    // 1024
#define O_WU    18944    // 256
#define O_H     19200    // 256
#define O_RD    19456    // 256
#define O_PR    19712    // 512
#define O_WP    20224    // 40
#define O_EX    20264    // 16
#define O_SOFT  20280    // 16
#define O_LU    20296    // 4 (int)
#define O_PART  20300    // 16*264
#define K4_FLOATS 24524
#define K4_BYTES (K4_FLOATS * 4)

__global__ __launch_bounds__(512) void k4_mem(
    const float* __restrict__ Wkp, const float* __restrict__ bkp,
    const float* __restrict__ Wout, const float* __restrict__ bout,
    float* __restrict__ out, int t)
{
    extern __shared__ float sm[];
    float* sM     = sm + O_M;
    float* sk     = sm + O_K;
    float* ssim   = sm + O_SIM;
    float* sww    = sm + O_WW;
    float* swu    = sm + O_WU;
    float* sh     = sm + O_H;
    float* sreads = sm + O_RD;
    float* spR    = sm + O_PR;
    float* swp    = sm + O_WP;
    float* sex    = sm + O_EX;
    float* ssoft  = sm + O_SOFT;
    int*   slu    = (int*)(sm + O_LU);
    float* spart  = sm + O_PART;

    const int b = blockIdx.x;
    const int tid = threadIdx.x;
    const int lane = tid & 31, wid = tid >> 5;

    if (tid < 256) {
        swu[tid] = g_wu[b * 256 + tid];
        sh[tid]  = g_h[b * 256 + tid];
    }
    {
        const float4* gm4 = (const float4*)(g_M + (size_t)b * 16384);
#pragma unroll
        for (int e = 0; e < 8; e++) {
            float4 v = gm4[e * 512 + tid];
            int gidx = (e * 512 + tid) * 4;
            int n = gidx >> 6, d = gidx & 63;
            float* dst = sM + n * 65 + d;
            dst[0] = v.x; dst[1] = v.y; dst[2] = v.z; dst[3] = v.w;
        }
    }
    __syncthreads();

    // kp GEMV: 16-way k-split
    {
        const int kbase = wid * 16;
        float hreg[16];
#pragma unroll
        for (int kk = 0; kk < 16; kk++) hreg[kk] = sh[kbase + kk];
#pragma unroll
        for (int g = 0; g < 9; g++) {
            int col = g * 32 + lane;
            if (col < 260) {
                const float* wp = Wkp + (size_t)kbase * 260 + col;
                float part = 0.0f;
#pragma unroll
                for (int kk = 0; kk < 16; kk++)
                    part += hreg[kk] * wp[(size_t)kk * 260];
                spart[wid * 264 + col] = part;
            }
        }
    }
    __syncthreads();
    if (tid < 260) {
        float s = bkp[tid];
#pragma unroll
        for (int w = 0; w < 16; w++) s += spart[w * 264 + tid];
        if (tid < 256) sk[tid] = tanhf(s);
        else sex[4 + (tid - 256)] = sigf(s);
    }
    __syncthreads();

    // key norms (warps 0-3) || top-4 least-used (warp 4)
    if (wid < 4) {
        float v0 = sk[wid * 64 + lane], v1 = sk[wid * 64 + lane + 32];
        float s = v0 * v0 + v1 * v1;
#pragma unroll
        for (int o = 16; o > 0; o >>= 1) s += __shfl_xor_sync(0xffffffffu, s, o);
        if (lane == 0) sex[wid] = 1.0f / (sqrtf(s) + EPSF);
    } else if (wid == 4) {
        float v[8];
#pragma unroll
        for (int j = 0; j < 8; j++) v[j] = swu[j * 32 + lane];
#pragma unroll
        for (int r = 0; r < 4; r++) {
            float bv = v[0]; int bi = lane;
#pragma unroll
            for (int j = 1; j < 8; j++) {
                int idx = j * 32 + lane;
                if (v[j] < bv) { bv = v[j]; bi = idx; }
            }
#pragma unroll
            for (int o = 16; o > 0; o >>= 1) {
                float ov = __shfl_xor_sync(0xffffffffu, bv, o);
                int   oi = __shfl_xor_sync(0xffffffffu, bi, o);
                if (ov < bv || (ov == bv && oi < bi)) { bv = ov; bi = oi; }
            }
            if (lane == 0) slu[r] = bi;
#pragma unroll
            for (int j = 0; j < 8; j++)
                if (bi == j * 32 + lane) v[j] = 3.0e38f;
        }
    }
    __syncthreads();

    if (tid < 256) {
        float a0 = sex[4], a1 = sex[5], a2 = sex[6], a3 = sex[7];
        const float* wr = g_wr + (size_t)b * 1024;
        float4 w;
        w.x = a0 * wr[tid]       + (1.0f - a0) * ((tid == slu[0]) ? 1.0f : 0.0f);
        w.y = a1 * wr[256 + tid] + (1.0f - a1) * ((tid == slu[1]) ? 1.0f : 0.0f);
        w.z = a2 * wr[512 + tid] + (1.0f - a2) * ((tid == slu[2]) ? 1.0f : 0.0f);
        w.w = a3 * wr[768 + tid] + (1.0f - a3) * ((tid == slu[3]) ? 1.0f : 0.0f);
        *(float4*)&sww[tid * 4] = w;
    }
    __syncthreads();

    // erase + additive write; persist M
    {
        const int d = tid & 63, nb = tid >> 6;
        const int lu0 = slu[0];
        const float k0 = sk[d], k1 = sk[64 + d], k2 = sk[128 + d], k3 = sk[192 + d];
        float* gmw = g_M + (size_t)b * 16384;
#pragma unroll 4
        for (int e = 0; e < 32; e++) {
            int n = e * 8 + nb;
            float4 w = *(float4*)&sww[n * 4];
            float v = (n == lu0) ? 0.0f : sM[n * 65 + d];
            v += w.x * k0 + w.y * k1 + w.z * k2 + w.w * k3;
            sM[n * 65 + d] = v;
            gmw[n * 64 + d] = v;
        }
    }
    __syncthreads();

    // row norms + cosine sims: 2 threads per row
    {
        const int row = tid >> 1, hf = tid & 1;
        const float* mrow = sM + row * 65 + hf * 32;
        const float* kb = sk + hf * 32;
        float s = 0, d0 = 0, d1 = 0, d2 = 0, d3 = 0;
#pragma unroll
        for (int dd = 0; dd < 32; dd += 4) {
            float4 kk0 = *(const float4*)&kb[dd];
            float4 kk1 = *(const float4*)&kb[64 + dd];
            float4 kk2 = *(const float4*)&kb[128 + dd];
            float4 kk3 = *(const float4*)&kb[192 + dd];
            float m0 = mrow[dd], m1 = mrow[dd + 1], m2 = mrow[dd + 2], m3 = mrow[dd + 3];
            s  += m0 * m0 + m1 * m1 + m2 * m2 + m3 * m3;
            d0 += m0 * kk0.x + m1 * kk0.y + m2 * kk0.z + m3 * kk0.w;
            d1 += m0 * kk1.x + m1 * kk1.y + m2 * kk1.z + m3 * kk1.w;
            d2 += m0 * kk2.x + m1 * kk2.y + m2 * kk2.z + m3 * kk2.w;
            d3 += m0 * kk3.x + m1 * kk3.y + m2 * kk3.z + m3 * kk3.w;
        }
        s  += __shfl_xor_sync(0xffffffffu, s, 1);
        d0 += __shfl_xor_sync(0xffffffffu, d0, 1);
        d1 += __shfl_xor_sync(0xffffffffu, d1, 1);
        d2 += __shfl_xor_sync(0xffffffffu, d2, 1);
        d3 += __shfl_xor_sync(0xffffffffu, d3, 1);
        if (hf == 0) {
            float inv = 1.0f / (sqrtf(s) + EPSF);
            ssim[row]       = d0 * inv * sex[0];
            ssim[256 + row] = d1 * inv * sex[1];
            ssim[512 + row] = d2 * inv * sex[2];
            ssim[768 + row] = d3 * inv * sex[3];
        }
    }
    __syncthreads();

    // softmax per head (warp-shuffle)
    float e0, e1, e2, e3;
    float* srow = 0;
    int gH = 0;
    if (tid < 256) {
        gH = tid >> 6;
        const int j = tid & 63;
        srow = ssim + gH * 256 + j;
        float v0 = srow[0], v1 = srow[64], v2 = srow[128], v3 = srow[192];
        float mx = fmaxf(fmaxf(v0, v1), fmaxf(v2, v3));
#pragma unroll
        for (int o = 16; o > 0; o >>= 1) mx = fmaxf(mx, __shfl_xor_sync(0xffffffffu, mx, o));
        if (lane == 0) ssoft[gH * 2 + ((tid >> 5) & 1)] = mx;
        e0 = v0; e1 = v1; e2 = v2; e3 = v3;
    }
    __syncthreads();
    if (tid < 256) {
        float mx = fmaxf(ssoft[gH * 2], ssoft[gH * 2 + 1]);
        e0 = expf(e0 - mx); e1 = expf(e1 - mx); e2 = expf(e2 - mx); e3 = expf(e3 - mx);
        float sum = e0 + e1 + e2 + e3;
#pragma unroll
        for (int o = 16; o > 0; o >>= 1) sum += __shfl_xor_sync(0xffffffffu, sum, o);
        if (lane == 0) ssoft[8 + gH * 2 + ((tid >> 5) & 1)] = sum;
    }
    __syncthreads();
    if (tid < 256) {
        float inv = 1.0f / (ssoft[8 + gH * 2] + ssoft[8 + gH * 2 + 1]);
        srow[0] = e0 * inv; srow[64] = e1 * inv; srow[128] = e2 * inv; srow[192] = e3 * inv;
        float wrs = (e0 + e1 + e2 + e3) * inv;
        float4 w = *(float4*)&sww[tid * 4];
        g_wu[b * 256 + tid] = GAMMA * swu[tid] + wrs + (w.x + w.y + w.z + w.w);
    }
    __syncthreads();
    if (tid < 256) {
        float* gwr = g_wr + (size_t)b * 1024;
        gwr[tid] = ssim[tid]; gwr[256 + tid] = ssim[256 + tid];
        gwr[512 + tid] = ssim[512 + tid]; gwr[768 + tid] = ssim[768 + tid];
    }

    // reads[r][d]
    {
        const int half = tid >> 8;
        const int r = (tid >> 6) & 3, dd = tid & 63;
        const float* wr2 = ssim + r * 256 + half * 128;
        const float* mbase = sM + half * 128 * 65;
        float acc = 0.0f;
#pragma unroll 4
        for (int n = 0; n < 128; n += 4) {
            float4 w = *(const float4*)&wr2[n];
            acc += w.x * mbase[n * 65 + dd] + w.y * mbase[(n + 1) * 65 + dd]
                 + w.z * mbase[(n + 2) * 65 + dd] + w.w * mbase[(n + 3) * 65 + dd];
        }
        spR[tid] = acc;
    }
    __syncthreads();
    if (tid < 256) {
        float v = spR[tid] + spR[tid + 256];
        sreads[tid] = v;
        g_r[b * 256 + tid] = v;
    }
    __syncthreads();

    // output head
    if (tid < 256) {
        const float* w1 = Wout + (size_t)tid * 5;
        const float* w2 = Wout + (size_t)(256 + tid) * 5;
        float hv = sh[tid], rv = sreads[tid];
        float p0 = hv * w1[0] + rv * w2[0];
        float p1 = hv * w1[1] + rv * w2[1];
        float p2 = hv * w1[2] + rv * w2[2];
        float p3 = hv * w1[3] + rv * w2[3];
        float p4 = hv * w1[4] + rv * w2[4];
#pragma unroll
        for (int o = 16; o > 0; o >>= 1) {
            p0 += __shfl_xor_sync(0xffffffffu, p0, o);
            p1 += __shfl_xor_sync(0xffffffffu, p1, o);
            p2 += __shfl_xor_sync(0xffffffffu, p2, o);
            p3 += __shfl_xor_sync(0xffffffffu, p3, o);
            p4 += __shfl_xor_sync(0xffffffffu, p4, o);
        }
        if (lane == 0) {
            swp[wid * 5 + 0] = p0; swp[wid * 5 + 1] = p1; swp[wid * 5 + 2] = p2;
            swp[wid * 5 + 3] = p3; swp[wid * 5 + 4] = p4;
        }
    }
    __syncthreads();
    if (tid == 0) {
        float l[5];
#pragma unroll
        for (int c = 0; c < 5; c++) {
            float s = bout[c];
#pragma unroll
            for (int w = 0; w < 8; w++) s += swp[w * 5 + c];
            l[c] = s;
        }
        float mx = l[0];
#pragma unroll
        for (int c = 1; c < 5; c++) mx = fmaxf(mx, l[c]);
        float e[5], s = 0.0f;
#pragma unroll
        for (int c = 0; c < 5; c++) { e[c] = expf(l[c] - mx); s += e[c]; }
        float inv = 1.0f / s;
        float* o = out + ((size_t)b * TSTEPS + t) * 5;
#pragma unroll
        for (int c = 0; c < 5; c++) o[c] = e[c] * inv;
    }
}

// ---------- launch ----------
extern "C" void kernel_launch(void* const* d_in, const int* in_sizes, int n_in,
                              void* d_out, int out_size) {
    const float* X    = (const float*)d_in[0];
    const int*   tgt  = (const int*)d_in[1];
    const float* Wih  = (const float*)d_in[2];
    const float* Whh  = (const float*)d_in[3];
    const float* bl   = (const float*)d_in[4];
    const float* Wkp  = (const float*)d_in[5];
    const float* bkp  = (const float*)d_in[6];
    const float* Wout = (const float*)d_in[7];
    const float* bout = (const float*)d_in[8];
    float* out = (float*)d_out;

    cudaFuncSetAttribute(k4_mem, cudaFuncAttributeMaxDynamicSharedMemorySize, K4_BYTES);

    k_init<<<16384, 256>>>();
    k1_xw_tc<<<dim3(8, 100), 256>>>(X, tgt, Wih, bl);
    for (int t = 0; t < TSTEPS; t++) {
        k2_step<<<dim3(8, 16), 256>>>(Wih, Whh, t);
        k4_mem<<<256, 512, K4_BYTES>>>(Wkp, bkp, Wout, bout, out, t);
    }
}

// round 14
// speedup vs baseline: 1.2142x; 1.0348x over previous
#include <cuda_runtime.h>
#include <math.h>

#define BATCH 256
#define TSTEPS 50
#define INSZ 400
#define G4 1024
#define GAMMA 0.95f
#define EPSF 1e-8f

// ---------- device scratch ----------
__device__ float g_xw[TSTEPS * BATCH * G4];
__device__ float g_h[BATCH * 256];
__device__ float g_c[BATCH * 256];
__device__ float g_r[BATCH * 256];
__device__ float g_M[BATCH * 256 * 64];
__device__ float g_wr[BATCH * 4 * 256];
__device__ float g_wu[BATCH * 256];

__device__ __forceinline__ float sigf(float x) { return 1.0f / (1.0f + expf(-x)); }

__device__ __forceinline__ unsigned tf32cvt(float f) {
    unsigned u;
    asm("cvt.rna.tf32.f32 %0, %1;" : "=r"(u) : "f"(f));
    return u;
}
__device__ __forceinline__ void mma_tf32(
    float& d0, float& d1, float& d2, float& d3,
    unsigned a0, unsigned a1, unsigned a2, unsigned a3,
    unsigned b0, unsigned b1)
{
    asm("mma.sync.aligned.m16n8k8.row.col.f32.tf32.tf32.f32 "
        "{%0,%1,%2,%3}, {%4,%5,%6,%7}, {%8,%9}, {%0,%1,%2,%3};"
        : "+f"(d0), "+f"(d1), "+f"(d2), "+f"(d3)
        : "r"(a0), "r"(a1), "r"(a2), "r"(a3), "r"(b0), "r"(b1));
}

// ---------- init ----------
__global__ void k_init() {
    int i = blockIdx.x * blockDim.x + threadIdx.x;
    if (i < BATCH * 256 * 64) g_M[i] = 1e-6f;
    if (i < BATCH * 1024) g_wr[i] = 1.0f / 256.0f;
    if (i < BATCH * 256) {
        g_h[i] = 0.0f; g_c[i] = 0.0f; g_r[i] = 0.0f;
        g_wu[i] = 1.0f / 256.0f;
    }
}

// ---------- K1: tf32 tensor-core GEMM (R13 version) ----------
__global__ __launch_bounds__(256) void k1_xw_tc(
    const float* __restrict__ X, const int* __restrict__ tgt,
    const float* __restrict__ Wih, const float* __restrict__ bl)
{
    __shared__ unsigned As[2][128][20];
    __shared__ unsigned Bs[2][16][136];
    __shared__ float bls[128];

    const int tid = threadIdx.x;
    const int lane = tid & 31, warp = tid >> 5;
    const int wm = warp & 3, wn = warp >> 2;
    const int g = lane >> 2, tg = lane & 3;
    const int m0 = blockIdx.y * 128, n0 = blockIdx.x * 128;

    if (tid < 128) bls[tid] = bl[n0 + tid];

    const int e0 = tid, e1 = tid + 256;
    const int arw0 = e0 >> 2, acq0 = e0 & 3;
    const int arw1 = e1 >> 2, acq1 = e1 & 3;
    const int bk0 = e0 >> 5, bnq0 = e0 & 31;
    const int bk1 = e1 >> 5, bnq1 = e1 & 31;

    float4 ax0, ax1, bx0, bx1;
    ax0 = *(const float4*)(X + (size_t)(m0 + arw0) * INSZ + acq0 * 4);
    ax1 = *(const float4*)(X + (size_t)(m0 + arw1) * INSZ + acq1 * 4);
    bx0 = *(const float4*)(Wih + (size_t)bk0 * G4 + n0 + bnq0 * 4);
    bx1 = *(const float4*)(Wih + (size_t)bk1 * G4 + n0 + bnq1 * 4);
    {
        uint4 u;
        u.x = tf32cvt(ax0.x); u.y = tf32cvt(ax0.y); u.z = tf32cvt(ax0.z); u.w = tf32cvt(ax0.w);
        *(uint4*)&As[0][arw0][acq0 * 4] = u;
        u.x = tf32cvt(ax1.x); u.y = tf32cvt(ax1.y); u.z = tf32cvt(ax1.z); u.w = tf32cvt(ax1.w);
        *(uint4*)&As[0][arw1][acq1 * 4] = u;
        u.x = tf32cvt(bx0.x); u.y = tf32cvt(bx0.y); u.z = tf32cvt(bx0.z); u.w = tf32cvt(bx0.w);
        *(uint4*)&Bs[0][bk0][bnq0 * 4] = u;
        u.x = tf32cvt(bx1.x); u.y = tf32cvt(bx1.y); u.z = tf32cvt(bx1.z); u.w = tf32cvt(bx1.w);
        *(uint4*)&Bs[0][bk1][bnq1 * 4] = u;
    }
    __syncthreads();

    float d[2][8][4];
#pragma unroll
    for (int i = 0; i < 2; i++)
#pragma unroll
        for (int j = 0; j < 8; j++)
#pragma unroll
            for (int q = 0; q < 4; q++) d[i][j][q] = 0.0f;

    for (int kt = 0; kt < 25; kt++) {
        const int cur = kt & 1;
        if (kt < 24) {
            const int kb = (kt + 1) * 16;
            ax0 = *(const float4*)(X + (size_t)(m0 + arw0) * INSZ + kb + acq0 * 4);
            ax1 = *(const float4*)(X + (size_t)(m0 + arw1) * INSZ + kb + acq1 * 4);
            bx0 = *(const float4*)(Wih + (size_t)(kb + bk0) * G4 + n0 + bnq0 * 4);
            bx1 = *(const float4*)(Wih + (size_t)(kb + bk1) * G4 + n0 + bnq1 * 4);
        }
#pragma unroll
        for (int ks = 0; ks < 2; ks++) {
            const int kk = ks * 8;
            unsigned af[2][4];
#pragma unroll
            for (int mt = 0; mt < 2; mt++) {
                const int r = wm * 32 + mt * 16 + g;
                af[mt][0] = As[cur][r][kk + tg];
                af[mt][1] = As[cur][r + 8][kk + tg];
                af[mt][2] = As[cur][r][kk + tg + 4];
                af[mt][3] = As[cur][r + 8][kk + tg + 4];
            }
#pragma unroll
            for (int nt = 0; nt < 8; nt++) {
                const int c = wn * 64 + nt * 8 + g;
                unsigned b0 = Bs[cur][kk + tg][c];
                unsigned b1 = Bs[cur][kk + tg + 4][c];
                mma_tf32(d[0][nt][0], d[0][nt][1], d[0][nt][2], d[0][nt][3],
                         af[0][0], af[0][1], af[0][2], af[0][3], b0, b1);
                mma_tf32(d[1][nt][0], d[1][nt][1], d[1][nt][2], d[1][nt][3],
                         af[1][0], af[1][1], af[1][2], af[1][3], b0, b1);
            }
        }
        if (kt < 24) {
            const int nxt = 1 - cur;
            uint4 u;
            u.x = tf32cvt(ax0.x); u.y = tf32cvt(ax0.y); u.z = tf32cvt(ax0.z); u.w = tf32cvt(ax0.w);
            *(uint4*)&As[nxt][arw0][acq0 * 4] = u;
            u.x = tf32cvt(ax1.x); u.y = tf32cvt(ax1.y); u.z = tf32cvt(ax1.z); u.w = tf32cvt(ax1.w);
            *(uint4*)&As[nxt][arw1][acq1 * 4] = u;
            u.x = tf32cvt(bx0.x); u.y = tf32cvt(bx0.y); u.z = tf32cvt(bx0.z); u.w = tf32cvt(bx0.w);
            *(uint4*)&Bs[nxt][bk0][bnq0 * 4] = u;
            u.x = tf32cvt(bx1.x); u.y = tf32cvt(bx1.y); u.z = tf32cvt(bx1.z); u.w = tf32cvt(bx1.w);
            *(uint4*)&Bs[nxt][bk1][bnq1 * 4] = u;
            __syncthreads();
        }
    }

#pragma unroll
    for (int mt = 0; mt < 2; mt++) {
#pragma unroll
        for (int rp = 0; rp < 2; rp++) {
            const int m = m0 + wm * 32 + mt * 16 + g + rp * 8;
            const int bb = m / TSTEPS, t = m % TSTEPS;
            const float* offrow = (t > 0) ? (Wih + (size_t)(400 + tgt[m - 1]) * G4) : (const float*)0;
            float* dst = g_xw + ((size_t)t * BATCH + bb) * G4 + n0;
#pragma unroll
            for (int nt = 0; nt < 8; nt++) {
                const int c = wn * 64 + nt * 8 + tg * 2;
                float v0 = d[mt][nt][rp * 2 + 0] + bls[c];
                float v1 = d[mt][nt][rp * 2 + 1] + bls[c + 1];
                if (offrow) { v0 += offrow[n0 + c]; v1 += offrow[n0 + c + 1]; }
                float2 v = make_float2(v0, v1);
                *(float2*)(dst + c) = v;
            }
        }
    }
}

// ---------- K2: recurrent GEMM + LSTM, double-buffered (R8 version) ----------
__global__ __launch_bounds__(256) void k2_step(
    const float* __restrict__ Wih, const float* __restrict__ Whh, int t)
{
    __shared__ float As2[2][16][34];
    __shared__ float Bs2[2][16][68];
    const int tid = threadIdx.x;
    const int tx = tid & 15, ty = tid >> 4;
    const int b0 = blockIdx.x * 32, u0 = blockIdx.y * 16;
    const int arow = tid >> 3, akq = tid & 7;
    const int bk = tid >> 4, bu = tid & 15;
    const float* WihR = Wih + (size_t)405 * G4;

    const int uP = u0 + tx;
    const int bP0 = b0 + ty * 2, bP1 = bP0 + 1;
    const float* xwA = g_xw + ((size_t)t * BATCH + bP0) * G4;
    const float* xwB = g_xw + ((size_t)t * BATCH + bP1) * G4;
    float xA0 = xwA[uP], xA1 = xwA[256 + uP], xA2 = xwA[512 + uP], xA3 = xwA[768 + uP];
    float xB0 = xwB[uP], xB1 = xwB[256 + uP], xB2 = xwB[512 + uP], xB3 = xwB[768 + uP];
    float cA = g_c[bP0 * 256 + uP], cB = g_c[bP1 * 256 + uP];

    {
        float2 av = *(const float2*)(g_r + (size_t)(b0 + arow) * 256 + akq * 2);
        As2[0][akq * 2][arow] = av.x; As2[0][akq * 2 + 1][arow] = av.y;
        const float* wrow = WihR + (size_t)bk * G4 + u0 + bu;
        Bs2[0][bk][bu * 4 + 0] = wrow[0];
        Bs2[0][bk][bu * 4 + 1] = wrow[256];
        Bs2[0][bk][bu * 4 + 2] = wrow[512];
        Bs2[0][bk][bu * 4 + 3] = wrow[768];
    }
    __syncthreads();

    float acc[2][4] = {};
    for (int kt = 0; kt < 32; kt++) {
        const int cur = kt & 1;
        float2 avn = make_float2(0.f, 0.f);
        float bgn0 = 0.f, bgn1 = 0.f, bgn2 = 0.f, bgn3 = 0.f;
        if (kt < 31) {
            const int kn = kt + 1;
            const float* src = (kn < 16) ? g_r : g_h;
            avn = *(const float2*)(src + (size_t)(b0 + arow) * 256 + (kn & 15) * 16 + akq * 2);
            const float* W = (kn < 16) ? WihR : Whh;
            const float* wrow = W + (size_t)((kn & 15) * 16 + bk) * G4 + u0 + bu;
            bgn0 = wrow[0]; bgn1 = wrow[256]; bgn2 = wrow[512]; bgn3 = wrow[768];
        }
#pragma unroll
        for (int k = 0; k < 16; k++) {
            float a0 = As2[cur][k][ty * 2], a1 = As2[cur][k][ty * 2 + 1];
            float4 b = *(float4*)&Bs2[cur][k][tx * 4];
            acc[0][0] += a0 * b.x; acc[0][1] += a0 * b.y; acc[0][2] += a0 * b.z; acc[0][3] += a0 * b.w;
            acc[1][0] += a1 * b.x; acc[1][1] += a1 * b.y; acc[1][2] += a1 * b.z; acc[1][3] += a1 * b.w;
        }
        if (kt < 31) {
            const int nxt = 1 - cur;
            As2[nxt][akq * 2][arow] = avn.x; As2[nxt][akq * 2 + 1][arow] = avn.y;
            Bs2[nxt][bk][bu * 4 + 0] = bgn0;
            Bs2[nxt][bk][bu * 4 + 1] = bgn1;
            Bs2[nxt][bk][bu * 4 + 2] = bgn2;
            Bs2[nxt][bk][bu * 4 + 3] = bgn3;
            __syncthreads();
        }
    }
    {
        float gi = acc[0][0] + xA0, gf = acc[0][1] + xA1, gg = acc[0][2] + xA2, go = acc[0][3] + xA3;
        float cc = sigf(gf) * cA + sigf(gi) * tanhf(gg);
        g_c[bP0 * 256 + uP] = cc;
        g_h[bP0 * 256 + uP] = sigf(go) * tanhf(cc);
    }
    {
        float gi = acc[1][0] + xB0, gf = acc[1][1] + xB1, gg = acc[1][2] + xB2, go = acc[1][3] + xB3;
        float cc = sigf(gf) * cB + sigf(gi) * tanhf(gg);
        g_c[bP1 * 256 + uP] = cc;
        g_h[bP1 * 256 + uP] = sigf(go) * tanhf(cc);
    }
}

// ---------- K4: 2 batches per CTA, 1024 threads; Wkp read once per CTA ----------
// smem float offsets
#define Q_M     0        // [2][256*65] = 33280
#define Q_PART  33280    // [2][16][264] = 8448
#define Q_K     41728    // [2][256]
#define Q_SIM   42240    // [2][1024]
#define Q_WW    44288    // [2][1024]
#define Q_WU    46336    // [2][256]
#define Q_H     46848    // [2][256]
#define Q_RD    47360    // [2][256]
#define Q_PR    47872    // [2][512]
#define Q_WP    48896    // [2][40]
#define Q_EX    48976    // [2][16]
#define Q_SOFT  49008    // [2][16]
#define Q_LU    49040    // int [2][4]
#define K4_FLOATS 49048
#define K4_BYTES (K4_FLOATS * 4)

__global__ __launch_bounds__(1024) void k4_mem(
    const float* __restrict__ Wkp, const float* __restrict__ bkp,
    const float* __restrict__ Wout, const float* __restrict__ bout,
    float* __restrict__ out, int t)
{
    extern __shared__ float sm[];
    float* sMall   = sm + Q_M;
    float* spart   = sm + Q_PART;
    float* skall   = sm + Q_K;
    float* ssimall = sm + Q_SIM;
    float* swwall  = sm + Q_WW;
    float* swuall  = sm + Q_WU;
    float* shall   = sm + Q_H;
    float* srdall  = sm + Q_RD;
    float* spRall  = sm + Q_PR;
    float* swpall  = sm + Q_WP;
    float* sexall  = sm + Q_EX;
    float* ssfall  = sm + Q_SOFT;
    int*   sluall  = (int*)(sm + Q_LU);

    const int tid = threadIdx.x;
    const int half = tid >> 9, lt = tid & 511;
    const int lane = tid & 31;
    const int widl = lt >> 5;                 // warp index within half (0..15)
    const int b = blockIdx.x * 2 + half;

    float* sM     = sMall + half * 16640;
    float* sk     = skall + half * 256;
    float* ssim   = ssimall + half * 1024;
    float* sww    = swwall + half * 1024;
    float* swu    = swuall + half * 256;
    float* sh     = shall + half * 256;
    float* sreads = srdall + half * 256;
    float* spR    = spRall + half * 512;
    float* swp    = swpall + half * 40;
    float* sex    = sexall + half * 16;
    float* ssoft  = ssfall + half * 16;
    int*   slu    = sluall + half * 4;

    // ---- phase 0: per-half h/wu loads ----
    if (lt < 256) {
        swu[lt] = g_wu[b * 256 + lt];
        sh[lt]  = g_h[b * 256 + lt];
    }
    __syncthreads();

    // ---- phase 1: warps 0-15 = shared Wkp GEMV (both batches); warps 16-31 = M load (both batches) ----
    if (tid < 512) {
        const int w = tid >> 5;               // 0..15
        const int kbase = w * 16;
        float h0[16], h1[16];
#pragma unroll
        for (int kk = 0; kk < 16; kk++) {
            h0[kk] = shall[kbase + kk];
            h1[kk] = shall[256 + kbase + kk];
        }
#pragma unroll
        for (int g = 0; g < 9; g++) {
            int col = g * 32 + lane;
            if (col < 260) {
                const float* wp = Wkp + (size_t)kbase * 260 + col;
                float p0 = 0.0f, p1 = 0.0f;
#pragma unroll
                for (int kk = 0; kk < 16; kk++) {
                    float wv = wp[(size_t)kk * 260];
                    p0 += h0[kk] * wv;
                    p1 += h1[kk] * wv;
                }
                spart[w * 264 + col] = p0;
                spart[4224 + w * 264 + col] = p1;
            }
        }
    } else {
        const int tm = tid - 512;             // 0..511
        const int cta0 = blockIdx.x * 2;
        const float4* gm4 = (const float4*)(g_M + (size_t)cta0 * 16384);
#pragma unroll
        for (int e = 0; e < 16; e++) {
            int gi = e * 512 + tm;            // 0..8191 float4s (2 batches)
            int bb = gi >> 12;                // 0/1
            int idx = gi & 4095;
            float4 v = gm4[(size_t)bb * 4096 + idx];
            int n = (idx * 4) >> 6, dd = (idx * 4) & 63;
            float* dst = sMall + bb * 16640 + n * 65 + dd;
            dst[0] = v.x; dst[1] = v.y; dst[2] = v.z; dst[3] = v.w;
        }
    }
    __syncthreads();

    // ---- kp partial sum + activations (per half) ----
    if (lt < 260) {
        float s = bkp[lt];
        const float* sp = spart + half * 4224;
#pragma unroll
        for (int w = 0; w < 16; w++) s += sp[w * 264 + lt];
        if (lt < 256) sk[lt] = tanhf(s);
        else sex[4 + (lt - 256)] = sigf(s);
    }
    __syncthreads();

    // ---- key norms (warps 0-3 of half) || top-4 least-used (warp 4 of half) ----
    if (widl < 4) {
        float v0 = sk[widl * 64 + lane], v1 = sk[widl * 64 + lane + 32];
        float s = v0 * v0 + v1 * v1;
#pragma unroll
        for (int o = 16; o > 0; o >>= 1) s += __shfl_xor_sync(0xffffffffu, s, o);
        if (lane == 0) sex[widl] = 1.0f / (sqrtf(s) + EPSF);
    } else if (widl == 4) {
        float v[8];
#pragma unroll
        for (int j = 0; j < 8; j++) v[j] = swu[j * 32 + lane];
#pragma unroll
        for (int r = 0; r < 4; r++) {
            float bv = v[0]; int bi = lane;
#pragma unroll
            for (int j = 1; j < 8; j++) {
                int idx = j * 32 + lane;
                if (v[j] < bv) { bv = v[j]; bi = idx; }
            }
#pragma unroll
            for (int o = 16; o > 0; o >>= 1) {
                float ov = __shfl_xor_sync(0xffffffffu, bv, o);
                int   oi = __shfl_xor_sync(0xffffffffu, bi, o);
                if (ov < bv || (ov == bv && oi < bi)) { bv = ov; bi = oi; }
            }
            if (lane == 0) slu[r] = bi;
#pragma unroll
            for (int j = 0; j < 8; j++)
                if (bi == j * 32 + lane) v[j] = 3.0e38f;
        }
    }
    __syncthreads();

    // ---- write weights w_w[n][r] ----
    if (lt < 256) {
        float a0 = sex[4], a1 = sex[5], a2 = sex[6], a3 = sex[7];
        const float* wr = g_wr + (size_t)b * 1024;
        float4 w;
        w.x = a0 * wr[lt]       + (1.0f - a0) * ((lt == slu[0]) ? 1.0f : 0.0f);
        w.y = a1 * wr[256 + lt] + (1.0f - a1) * ((lt == slu[1]) ? 1.0f : 0.0f);
        w.z = a2 * wr[512 + lt] + (1.0f - a2) * ((lt == slu[2]) ? 1.0f : 0.0f);
        w.w = a3 * wr[768 + lt] + (1.0f - a3) * ((lt == slu[3]) ? 1.0f : 0.0f);
        *(float4*)&sww[lt * 4] = w;
    }
    __syncthreads();

    // ---- erase + additive write; persist M ----
    {
        const int d = lt & 63, nb = lt >> 6;
        const int lu0 = slu[0];
        const float k0 = sk[d], k1 = sk[64 + d], k2 = sk[128 + d], k3 = sk[192 + d];
        float* gmw = g_M + (size_t)b * 16384;
#pragma unroll 4
        for (int e = 0; e < 32; e++) {
            int n = e * 8 + nb;
            float4 w = *(float4*)&sww[n * 4];
            float v = (n == lu0) ? 0.0f : sM[n * 65 + d];
            v += w.x * k0 + w.y * k1 + w.z * k2 + w.w * k3;
            sM[n * 65 + d] = v;
            gmw[n * 64 + d] = v;
        }
    }
    __syncthreads();

    // ---- row norms + cosine sims: 2 threads per row ----
    {
        const int row = lt >> 1, hf = lt & 1;
        const float* mrow = sM + row * 65 + hf * 32;
        const float* kb = sk + hf * 32;
        float s = 0, d0 = 0, d1 = 0, d2 = 0, d3 = 0;
#pragma unroll
        for (int dd = 0; dd < 32; dd += 4) {
            float4 kk0 = *(const float4*)&kb[dd];
            float4 kk1 = *(const float4*)&kb[64 + dd];
            float4 kk2 = *(const float4*)&kb[128 + dd];
            float4 kk3 = *(const float4*)&kb[192 + dd];
            float m0 = mrow[dd], m1 = mrow[dd + 1], m2 = mrow[dd + 2], m3 = mrow[dd + 3];
            s  += m0 * m0 + m1 * m1 + m2 * m2 + m3 * m3;
            d0 += m0 * kk0.x + m1 * kk0.y + m2 * kk0.z + m3 * kk0.w;
            d1 += m0 * kk1.x + m1 * kk1.y + m2 * kk1.z + m3 * kk1.w;
            d2 += m0 * kk2.x + m1 * kk2.y + m2 * kk2.z + m3 * kk2.w;
            d3 += m0 * kk3.x + m1 * kk3.y + m2 * kk3.z + m3 * kk3.w;
        }
        s  += __shfl_xor_sync(0xffffffffu, s, 1);
        d0 += __shfl_xor_sync(0xffffffffu, d0, 1);
        d1 += __shfl_xor_sync(0xffffffffu, d1, 1);
        d2 += __shfl_xor_sync(0xffffffffu, d2, 1);
        d3 += __shfl_xor_sync(0xffffffffu, d3, 1);
        if (hf == 0) {
            float inv = 1.0f / (sqrtf(s) + EPSF);
            ssim[row]       = d0 * inv * sex[0];
            ssim[256 + row] = d1 * inv * sex[1];
            ssim[512 + row] = d2 * inv * sex[2];
            ssim[768 + row] = d3 * inv * sex[3];
        }
    }
    __syncthreads();

    // ---- softmax per head (warp-shuffle) ----
    float e0, e1, e2, e3;
    float* srow = 0;
    int gH = 0;
    if (lt < 256) {
        gH = lt >> 6;
        const int j = lt & 63;
        srow = ssim + gH * 256 + j;
        float v0 = srow[0], v1 = srow[64], v2 = srow[128], v3 = srow[192];
        float mx = fmaxf(fmaxf(v0, v1), fmaxf(v2, v3));
#pragma unroll
        for (int o = 16; o > 0; o >>= 1) mx = fmaxf(mx, __shfl_xor_sync(0xffffffffu, mx, o));
        if (lane == 0) ssoft[gH * 2 + ((lt >> 5) & 1)] = mx;
        e0 = v0; e1 = v1; e2 = v2; e3 = v3;
    }
    __syncthreads();
    if (lt < 256) {
        float mx = fmaxf(ssoft[gH * 2], ssoft[gH * 2 + 1]);
        e0 = expf(e0 - mx); e1 = expf(e1 - mx); e2 = expf(e2 - mx); e3 = expf(e3 - mx);
        float sum = e0 + e1 + e2 + e3;
#pragma unroll
        for (int o = 16; o > 0; o >>= 1) sum += __shfl_xor_sync(0xffffffffu, sum, o);
        if (lane == 0) ssoft[8 + gH * 2 + ((lt >> 5) & 1)] = sum;
    }
    __syncthreads();
    if (lt < 256) {
        float inv = 1.0f / (ssoft[8 + gH * 2] + ssoft[8 + gH * 2 + 1]);
        srow[0] = e0 * inv; srow[64] = e1 * inv; srow[128] = e2 * inv; srow[192] = e3 * inv;
        float wrs = (e0 + e1 + e2 + e3) * inv;
        float4 w = *(float4*)&sww[lt * 4];
        g_wu[b * 256 + lt] = GAMMA * swu[lt] + wrs + (w.x + w.y + w.z + w.w);
    }
    __syncthreads();
    if (lt < 256) {
        float* gwr = g_wr + (size_t)b * 1024;
        gwr[lt] = ssim[lt]; gwr[256 + lt] = ssim[256 + lt];
        gwr[512 + lt] = ssim[512 + lt]; gwr[768 + lt] = ssim[768 + lt];
    }

    // ---- reads[r][d]: per half, split n into halves ----
    {
        const int sub = lt >> 8;
        const int r = (lt >> 6) & 3, dd = lt & 63;
        const float* wr2 = ssim + r * 256 + sub * 128;
        const float* mbase = sM + sub * 128 * 65;
        float acc = 0.0f;
#pragma unroll 4
        for (int n = 0; n < 128; n += 4) {
            float4 w = *(const float4*)&wr2[n];
            acc += w.x * mbase[n * 65 + dd] + w.y * mbase[(n + 1) * 65 + dd]
                 + w.z * mbase[(n + 2) * 65 + dd] + w.w * mbase[(n + 3) * 65 + dd];
        }
        spR[lt] = acc;
    }
    __syncthreads();
    if (lt < 256) {
        float v = spR[lt] + spR[lt + 256];
        sreads[lt] = v;
        g_r[b * 256 + lt] = v;
    }
    __syncthreads();

    // ---- output head ----
    if (lt < 256) {
        const float* w1 = Wout + (size_t)lt * 5;
        const float* w2 = Wout + (size_t)(256 + lt) * 5;
        float hv = sh[lt], rv = sreads[lt];
        float p0 = hv * w1[0] + rv * w2[0];
        float p1 = hv * w1[1] + rv * w2[1];
        float p2 = hv * w1[2] + rv * w2[2];
        float p3 = hv * w1[3] + rv * w2[3];
        float p4 = hv * w1[4] + rv * w2[4];
#pragma unroll
        for (int o = 16; o > 0; o >>= 1) {
            p0 += __shfl_xor_sync(0xffffffffu, p0, o);
            p1 += __shfl_xor_sync(0xffffffffu, p1, o);
            p2 += __shfl_xor_sync(0xffffffffu, p2, o);
            p3 += __shfl_xor_sync(0xffffffffu, p3, o);
            p4 += __shfl_xor_sync(0xffffffffu, p4, o);
        }
        if (lane == 0) {
            swp[widl * 5 + 0] = p0; swp[widl * 5 + 1] = p1; swp[widl * 5 + 2] = p2;
            swp[widl * 5 + 3] = p3; swp[widl * 5 + 4] = p4;
        }
    }
    __syncthreads();
    if (lt == 0) {
        float l[5];
#pragma unroll
        for (int c = 0; c < 5; c++) {
            float s = bout[c];
#pragma unroll
            for (int w = 0; w < 8; w++) s += swp[w * 5 + c];
            l[c] = s;
        }
        float mx = l[0];
#pragma unroll
        for (int c = 1; c < 5; c++) mx = fmaxf(mx, l[c]);
        float e[5], s = 0.0f;
#pragma unroll
        for (int c = 0; c < 5; c++) { e[c] = expf(l[c] - mx); s += e[c]; }
        float inv = 1.0f / s;
        float* o = out + ((size_t)b * TSTEPS + t) * 5;
#pragma unroll
        for (int c = 0; c < 5; c++) o[c] = e[c] * inv;
    }
}

// ---------- launch ----------
extern "C" void kernel_launch(void* const* d_in, const int* in_sizes, int n_in,
                              void* d_out, int out_size) {
    const float* X    = (const float*)d_in[0];
    const int*   tgt  = (const int*)d_in[1];
    const float* Wih  = (const float*)d_in[2];
    const float* Whh  = (const float*)d_in[3];
    const float* bl   = (const float*)d_in[4];
    const float* Wkp  = (const float*)d_in[5];
    const float* bkp  = (const float*)d_in[6];
    const float* Wout = (const float*)d_in[7];
    const float* bout = (const float*)d_in[8];
    float* out = (float*)d_out;

    cudaFuncSetAttribute(k4_mem, cudaFuncAttributeMaxDynamicSharedMemorySize, K4_BYTES);

    k_init<<<16384, 256>>>();
    k1_xw_tc<<<dim3(8, 100), 256>>>(X, tgt, Wih, bl);
    for (int t = 0; t < TSTEPS; t++) {
        k2_step<<<dim3(8, 16), 256>>>(Wih, Whh, t);
        k4_mem<<<128, 1024, K4_BYTES>>>(Wkp, bkp, Wout, bout, out, t);
    }
}